// round 3
// baseline (speedup 1.0000x reference)
#include <cuda_runtime.h>
#include <math.h>

// Problem constants
#define Bx  2
#define Sx  4096
#define Dx  512
#define Hx  8
#define DKx 64
#define SWx 128   // Sx/32 mask words per row
#define PD  68    // attn smem row stride (68 = 4 mod 32 -> conflict-free frag rows)

// GEMM tiling
#define PDA 36    // A stage row stride (36 = 4 mod 32)
#define PDW 132   // W stage row stride (132 = 4 mod 32)

// Scratch (no cudaMalloc allowed)
__device__ float    g_Qp[Bx * Sx * Dx];
__device__ float    g_Kp[Bx * Sx * Dx];
__device__ float    g_Vp[Bx * Sx * Dx];
__device__ float    g_AO[Bx * Sx * Dx];
__device__ unsigned g_mb[Bx * Sx * SWx];

// ---------------------------------------------------------------------------
// Helpers
// ---------------------------------------------------------------------------
__device__ __forceinline__ float tf32r(float x) {
    unsigned u;
    asm("cvt.rna.tf32.f32 %0, %1;" : "=r"(u) : "f"(x));
    return __uint_as_float(u);
}
__device__ __forceinline__ void mma8(float* c, unsigned a0, unsigned a1,
                                     unsigned a2, unsigned a3,
                                     unsigned b0, unsigned b1) {
    asm volatile(
        "mma.sync.aligned.m16n8k8.row.col.f32.tf32.tf32.f32 "
        "{%0,%1,%2,%3}, {%4,%5,%6,%7}, {%8,%9}, {%0,%1,%2,%3};\n"
        : "+f"(c[0]), "+f"(c[1]), "+f"(c[2]), "+f"(c[3])
        : "r"(a0), "r"(a1), "r"(a2), "r"(a3), "r"(b0), "r"(b1));
}
#define ASU(x) __float_as_uint(x)

// ---------------------------------------------------------------------------
// 1) mask (int32 [B,S,S]) -> bitmask. One coalesced pass.
// ---------------------------------------------------------------------------
__global__ void mask_bits_kernel(const int* __restrict__ mask) {
    int idx = blockIdx.x * 256 + threadIdx.x;
    int m = mask[idx];
    unsigned w = __ballot_sync(0xffffffffu, m != 0);
    if ((threadIdx.x & 31) == 0) g_mb[idx >> 5] = w;
}

// ---------------------------------------------------------------------------
// 2) tf32 MMA GEMM body: C[8192,512] = A[8192,512] @ W[512,512].
//    CTA tile 128x128, 8 warps (32x64 each), K-chunk 32.
//    A staged [m][k], W staged NATURAL [k][n] (conflict-free stores).
// ---------------------------------------------------------------------------
__device__ __forceinline__ void gemm_body(const float* __restrict__ A,
                                          const float* __restrict__ W,
                                          float* __restrict__ C) {
    __shared__ __align__(16) float As[128 * PDA];
    __shared__ __align__(16) float Ws[32 * PDW];

    const int tid = threadIdx.x, warp = tid >> 5, lane = tid & 31;
    const int g = lane >> 2, t = lane & 3;
    const int m0 = blockIdx.y << 7, n0 = blockIdx.x << 7;
    const int wm = (warp & 3) << 5, wn = (warp >> 2) << 6;

    float acc[2][8][4] = {};

    for (int k0 = 0; k0 < Dx; k0 += 32) {
        __syncthreads();
#pragma unroll
        for (int u = 0; u < 4; u++) {
            int f = tid + (u << 8);
            int r = f >> 3, kv = (f & 7) << 2;
            float4 a4 = *(const float4*)(A + (size_t)(m0 + r) * Dx + k0 + kv);
            *(float4*)&As[r * PDA + kv] =
                make_float4(tf32r(a4.x), tf32r(a4.y), tf32r(a4.z), tf32r(a4.w));
            int kk = f >> 5, nv = (f & 31) << 2;
            float4 w4 = *(const float4*)(W + (size_t)(k0 + kk) * Dx + n0 + nv);
            *(float4*)&Ws[kk * PDW + nv] =
                make_float4(tf32r(w4.x), tf32r(w4.y), tf32r(w4.z), tf32r(w4.w));
        }
        __syncthreads();
#pragma unroll
        for (int ks = 0; ks < 4; ks++) {
            unsigned a[2][4];
#pragma unroll
            for (int mf = 0; mf < 2; mf++) {
                int rb = (wm + (mf << 4) + g) * PDA + (ks << 3) + t;
                a[mf][0] = ASU(As[rb]);
                a[mf][1] = ASU(As[rb + 8 * PDA]);
                a[mf][2] = ASU(As[rb + 4]);
                a[mf][3] = ASU(As[rb + 8 * PDA + 4]);
            }
#pragma unroll
            for (int nt = 0; nt < 8; nt++) {
                int cb = ((ks << 3) + t) * PDW + wn + (nt << 3) + g;
                unsigned b0 = ASU(Ws[cb]);
                unsigned b1 = ASU(Ws[cb + 4 * PDW]);
                mma8(acc[0][nt], a[0][0], a[0][1], a[0][2], a[0][3], b0, b1);
                mma8(acc[1][nt], a[1][0], a[1][1], a[1][2], a[1][3], b0, b1);
            }
        }
    }
#pragma unroll
    for (int mf = 0; mf < 2; mf++)
#pragma unroll
        for (int nt = 0; nt < 8; nt++) {
            int row = m0 + wm + (mf << 4) + g;
            int col = n0 + wn + (nt << 3) + 2 * t;
            *(float2*)(C + (size_t)row * Dx + col) =
                make_float2(acc[mf][nt][0], acc[mf][nt][1]);
            *(float2*)(C + (size_t)(row + 8) * Dx + col) =
                make_float2(acc[mf][nt][2], acc[mf][nt][3]);
        }
}

__global__ __launch_bounds__(256, 2) void qkv_gemm(
    const float* __restrict__ q, const float* __restrict__ k,
    const float* __restrict__ v, const float* __restrict__ wq,
    const float* __restrict__ wk, const float* __restrict__ wv)
{
    const float *A, *W;
    float* C;
    if (blockIdx.z == 0)      { A = q; W = wq; C = g_Qp; }
    else if (blockIdx.z == 1) { A = k; W = wk; C = g_Kp; }
    else                      { A = v; W = wv; C = g_Vp; }
    gemm_body(A, W, C);
}

__global__ __launch_bounds__(256, 2) void out_gemm(
    const float* __restrict__ A, const float* __restrict__ W,
    float* __restrict__ C)
{
    gemm_body(A, W, C);
}

// ---------------------------------------------------------------------------
// 3) Flash attention, tf32 MMA. CTA = (b, h, 128 q rows), 8 warps.
//    K and V both staged NATURAL [s][d] (conflict-free float4 stores).
//    Each warp owns 16 full score rows -> softmax needs shfl_xor 1,2 only.
// ---------------------------------------------------------------------------
__global__ __launch_bounds__(256, 2) void attn_mma() {
    extern __shared__ __align__(16) float sm[];
    float* Qs = sm;                      // [r][d]  128x68
    float* Ks = sm + 128 * PD;           // [c][d]   64x68
    float* Vs = sm + (128 + 64) * PD;    // [s][d]   64x68
    float* Ps = sm + (128 + 128) * PD;   // [r][s]  128x68

    const int tid = threadIdx.x, warp = tid >> 5, lane = tid & 31;
    const int g = lane >> 2, t = lane & 3;
    const int q0 = blockIdx.x << 7, h = blockIdx.y, b = blockIdx.z;
    const int rw = warp << 4;
    const size_t baseQ  = ((size_t)b * Sx + q0) * Dx + (size_t)h * DKx;
    const size_t baseKV = (size_t)b * Sx * Dx + (size_t)h * DKx;

    // Stage Q (tf32)
#pragma unroll
    for (int u = 0; u < 8; u++) {
        int f = tid + (u << 8);
        int r = f >> 4, dv = (f & 15) << 2;
        float4 q4 = *(const float4*)(g_Qp + baseQ + (size_t)r * Dx + dv);
        *(float4*)&Qs[r * PD + dv] =
            make_float4(tf32r(q4.x), tf32r(q4.y), tf32r(q4.z), tf32r(q4.w));
    }

    float o[8][4] = {};
    float mr0 = -INFINITY, mr1 = -INFINITY, l0 = 0.f, l1 = 0.f;
    const size_t mb0 = ((size_t)b * Sx + q0 + rw + g) * SWx;
    const size_t mb1 = mb0 + (size_t)8 * SWx;

    for (int kt = 0; kt < Sx; kt += 64) {
        __syncthreads();  // all warps done reading previous K/V tiles
#pragma unroll
        for (int u = 0; u < 4; u++) {
            int f = tid + (u << 8);
            int r = f >> 4, dv = (f & 15) << 2;
            size_t gofs = baseKV + (size_t)(kt + r) * Dx + dv;
            float4 k4 = *(const float4*)(g_Kp + gofs);
            *(float4*)&Ks[r * PD + dv] =
                make_float4(tf32r(k4.x), tf32r(k4.y), tf32r(k4.z), tf32r(k4.w));
            float4 v4 = *(const float4*)(g_Vp + gofs);
            *(float4*)&Vs[r * PD + dv] =
                make_float4(tf32r(v4.x), tf32r(v4.y), tf32r(v4.z), tf32r(v4.w));
        }
        __syncthreads();

        // S = Q @ K^T
        float sa[8][4] = {};
#pragma unroll
        for (int ks = 0; ks < 8; ks++) {
            int rb = (rw + g) * PD + (ks << 3) + t;
            unsigned a0 = ASU(Qs[rb]);
            unsigned a1 = ASU(Qs[rb + 8 * PD]);
            unsigned a2 = ASU(Qs[rb + 4]);
            unsigned a3 = ASU(Qs[rb + 8 * PD + 4]);
#pragma unroll
            for (int nt = 0; nt < 8; nt++) {
                int cb = ((nt << 3) + g) * PD + (ks << 3) + t;
                unsigned b0 = ASU(Ks[cb]);
                unsigned b1 = ASU(Ks[cb + 4]);
                mma8(sa[nt], a0, a1, a2, a3, b0, b1);
            }
        }

        // Scale + mask (masked -> -1e9, exact reference semantics)
        const int wi = kt >> 5;
        unsigned m00 = g_mb[mb0 + wi], m01 = g_mb[mb0 + wi + 1];
        unsigned m10 = g_mb[mb1 + wi], m11 = g_mb[mb1 + wi + 1];
#pragma unroll
        for (int nt = 0; nt < 8; nt++) {
            int c0 = (nt << 3) + 2 * t;
            unsigned wr0 = (c0 < 32) ? m00 : m01;
            unsigned wr1 = (c0 < 32) ? m10 : m11;
            int bit = c0 & 31;
            sa[nt][0] = ((wr0 >> bit) & 1u)       ? sa[nt][0] * 0.125f : -1e9f;
            sa[nt][1] = ((wr0 >> (bit + 1)) & 1u) ? sa[nt][1] * 0.125f : -1e9f;
            sa[nt][2] = ((wr1 >> bit) & 1u)       ? sa[nt][2] * 0.125f : -1e9f;
            sa[nt][3] = ((wr1 >> (bit + 1)) & 1u) ? sa[nt][3] * 0.125f : -1e9f;
        }

        // Online softmax (rows rw+g and rw+g+8)
        float t0 = -INFINITY, t1 = -INFINITY;
#pragma unroll
        for (int nt = 0; nt < 8; nt++) {
            t0 = fmaxf(t0, fmaxf(sa[nt][0], sa[nt][1]));
            t1 = fmaxf(t1, fmaxf(sa[nt][2], sa[nt][3]));
        }
        t0 = fmaxf(t0, __shfl_xor_sync(0xffffffffu, t0, 1));
        t0 = fmaxf(t0, __shfl_xor_sync(0xffffffffu, t0, 2));
        t1 = fmaxf(t1, __shfl_xor_sync(0xffffffffu, t1, 1));
        t1 = fmaxf(t1, __shfl_xor_sync(0xffffffffu, t1, 2));
        float mn0 = fmaxf(mr0, t0), mn1 = fmaxf(mr1, t1);
        float corr0 = __expf(mr0 - mn0), corr1 = __expf(mr1 - mn1);
        float ps0 = 0.f, ps1 = 0.f;
#pragma unroll
        for (int nt = 0; nt < 8; nt++) {
            float p0 = __expf(sa[nt][0] - mn0);
            float p1 = __expf(sa[nt][1] - mn0);
            float p2 = __expf(sa[nt][2] - mn1);
            float p3 = __expf(sa[nt][3] - mn1);
            ps0 += p0 + p1; ps1 += p2 + p3;
            int c0 = (nt << 3) + 2 * t;
            *(float2*)&Ps[(rw + g)     * PD + c0] = make_float2(tf32r(p0), tf32r(p1));
            *(float2*)&Ps[(rw + g + 8) * PD + c0] = make_float2(tf32r(p2), tf32r(p3));
        }
        ps0 += __shfl_xor_sync(0xffffffffu, ps0, 1);
        ps0 += __shfl_xor_sync(0xffffffffu, ps0, 2);
        ps1 += __shfl_xor_sync(0xffffffffu, ps1, 1);
        ps1 += __shfl_xor_sync(0xffffffffu, ps1, 2);
        l0 = l0 * corr0 + ps0;
        l1 = l1 * corr1 + ps1;
        mr0 = mn0; mr1 = mn1;
#pragma unroll
        for (int nt = 0; nt < 8; nt++) {
            o[nt][0] *= corr0; o[nt][1] *= corr0;
            o[nt][2] *= corr1; o[nt][3] *= corr1;
        }
        __syncwarp();  // P rows are warp-private

        // O += P @ V   (V natural [s][d]: b = V[8ks+t(+4)][8nt+g])
#pragma unroll
        for (int ks = 0; ks < 8; ks++) {
            int rb = (rw + g) * PD + (ks << 3) + t;
            unsigned a0 = ASU(Ps[rb]);
            unsigned a1 = ASU(Ps[rb + 8 * PD]);
            unsigned a2 = ASU(Ps[rb + 4]);
            unsigned a3 = ASU(Ps[rb + 8 * PD + 4]);
#pragma unroll
            for (int nt = 0; nt < 8; nt++) {
                int cb = ((ks << 3) + t) * PD + (nt << 3) + g;
                unsigned b0 = ASU(Vs[cb]);
                unsigned b1 = ASU(Vs[cb + 4 * PD]);
                mma8(o[nt], a0, a1, a2, a3, b0, b1);
            }
        }
    }

    // Normalize + store
    float i0 = 1.f / l0, i1 = 1.f / l1;
#pragma unroll
    for (int nt = 0; nt < 8; nt++) {
        int c0 = (nt << 3) + 2 * t;
        *(float2*)(g_AO + baseQ + (size_t)(rw + g)     * Dx + c0) =
            make_float2(o[nt][0] * i0, o[nt][1] * i0);
        *(float2*)(g_AO + baseQ + (size_t)(rw + g + 8) * Dx + c0) =
            make_float2(o[nt][2] * i1, o[nt][3] * i1);
    }
}

// ---------------------------------------------------------------------------
// Launch
// ---------------------------------------------------------------------------
extern "C" void kernel_launch(void* const* d_in, const int* in_sizes, int n_in,
                              void* d_out, int out_size) {
    const float* q    = (const float*)d_in[0];
    const float* k    = (const float*)d_in[1];
    const float* v    = (const float*)d_in[2];
    const int*   mask = (const int*)  d_in[3];
    const float* wq   = (const float*)d_in[4];
    const float* wk   = (const float*)d_in[5];
    const float* wv   = (const float*)d_in[6];
    const float* wo   = (const float*)d_in[7];

    float* AO;
    cudaGetSymbolAddress((void**)&AO, g_AO);

    // 1) mask compression
    mask_bits_kernel<<<(Bx * Sx * Sx) / 256, 256>>>(mask);

    // 2) fused Q/K/V projections (tf32 MMA, 128x128 tiles)
    qkv_gemm<<<dim3(Dx / 128, (Bx * Sx) / 128, 3), 256>>>(q, k, v, wq, wk, wv);

    // 3) attention (tf32 MMA flash, 128 q-rows per CTA)
    const int smem_bytes = (128 + 64 + 64 + 128) * PD * (int)sizeof(float);  // 104448
    cudaFuncSetAttribute(attn_mma,
                         cudaFuncAttributeMaxDynamicSharedMemorySize, smem_bytes);
    attn_mma<<<dim3(Sx / 128, Hx, Bx), 256, smem_bytes>>>();

    // 4) output projection -> d_out
    out_gemm<<<dim3(Dx / 128, (Bx * Sx) / 128), 256>>>(AO, wo, (float*)d_out);
}

// round 8
// speedup vs baseline: 2.5011x; 2.5011x over previous
#include <cuda_runtime.h>
#include <cuda_fp16.h>
#include <math.h>

// Problem constants
#define Bx  2
#define Sx  4096
#define Dx  512
#define Hx  8
#define DKx 64
#define SWx 128   // Sx/32 mask words per row

// GEMM tiling (tf32 path, unchanged from R3)
#define PDA 36    // A stage row stride (36 = 4 mod 32)
#define PDW 132   // W stage row stride (132 = 4 mod 32)

// Attention smem stride (halves): 72 -> ldmatrix phases conflict-free (9r mod 8)
#define KVS 72

// Scratch (no cudaMalloc allowed)
__device__ float    g_Qp[Bx * Sx * Dx];
__device__ float    g_Kp[Bx * Sx * Dx];
__device__ float    g_Vp[Bx * Sx * Dx];
__device__ float    g_AO[Bx * Sx * Dx];
__device__ unsigned g_mb[Bx * Sx * SWx];

// ---------------------------------------------------------------------------
// Helpers
// ---------------------------------------------------------------------------
__device__ __forceinline__ float tf32r(float x) {
    unsigned u;
    asm("cvt.rna.tf32.f32 %0, %1;" : "=r"(u) : "f"(x));
    return __uint_as_float(u);
}
__device__ __forceinline__ void mma8(float* c, unsigned a0, unsigned a1,
                                     unsigned a2, unsigned a3,
                                     unsigned b0, unsigned b1) {
    asm volatile(
        "mma.sync.aligned.m16n8k8.row.col.f32.tf32.tf32.f32 "
        "{%0,%1,%2,%3}, {%4,%5,%6,%7}, {%8,%9}, {%0,%1,%2,%3};\n"
        : "+f"(c[0]), "+f"(c[1]), "+f"(c[2]), "+f"(c[3])
        : "r"(a0), "r"(a1), "r"(a2), "r"(a3), "r"(b0), "r"(b1));
}
__device__ __forceinline__ void mma16(float* c, unsigned a0, unsigned a1,
                                      unsigned a2, unsigned a3,
                                      unsigned b0, unsigned b1) {
    asm volatile(
        "mma.sync.aligned.m16n8k16.row.col.f32.f16.f16.f32 "
        "{%0,%1,%2,%3}, {%4,%5,%6,%7}, {%8,%9}, {%0,%1,%2,%3};\n"
        : "+f"(c[0]), "+f"(c[1]), "+f"(c[2]), "+f"(c[3])
        : "r"(a0), "r"(a1), "r"(a2), "r"(a3), "r"(b0), "r"(b1));
}
__device__ __forceinline__ unsigned h2u(float a, float b) {
    __half2 h = __floats2half2_rn(a, b);
    return *reinterpret_cast<unsigned*>(&h);
}
__device__ __forceinline__ void ldsm4(unsigned& r0, unsigned& r1,
                                      unsigned& r2, unsigned& r3, unsigned addr) {
    asm volatile("ldmatrix.sync.aligned.m8n8.x4.shared.b16 {%0,%1,%2,%3}, [%4];"
                 : "=r"(r0), "=r"(r1), "=r"(r2), "=r"(r3) : "r"(addr));
}
__device__ __forceinline__ void ldsm4t(unsigned& r0, unsigned& r1,
                                       unsigned& r2, unsigned& r3, unsigned addr) {
    asm volatile("ldmatrix.sync.aligned.m8n8.x4.trans.shared.b16 {%0,%1,%2,%3}, [%4];"
                 : "=r"(r0), "=r"(r1), "=r"(r2), "=r"(r3) : "r"(addr));
}
#define ASU(x) __float_as_uint(x)

// ---------------------------------------------------------------------------
// 1) mask (int32 [B,S,S]) -> bitmask. One coalesced pass.
// ---------------------------------------------------------------------------
__global__ void mask_bits_kernel(const int* __restrict__ mask) {
    int idx = blockIdx.x * 256 + threadIdx.x;
    int m = mask[idx];
    unsigned w = __ballot_sync(0xffffffffu, m != 0);
    if ((threadIdx.x & 31) == 0) g_mb[idx >> 5] = w;
}

// ---------------------------------------------------------------------------
// 2) tf32 MMA GEMM (unchanged from R3): 128x128 CTA tile, 8 warps, K-chunk 32
// ---------------------------------------------------------------------------
__device__ __forceinline__ void gemm_body(const float* __restrict__ A,
                                          const float* __restrict__ W,
                                          float* __restrict__ C) {
    __shared__ __align__(16) float As[128 * PDA];
    __shared__ __align__(16) float Ws[32 * PDW];

    const int tid = threadIdx.x, warp = tid >> 5, lane = tid & 31;
    const int g = lane >> 2, t = lane & 3;
    const int m0 = blockIdx.y << 7, n0 = blockIdx.x << 7;
    const int wm = (warp & 3) << 5, wn = (warp >> 2) << 6;

    float acc[2][8][4] = {};

    for (int k0 = 0; k0 < Dx; k0 += 32) {
        __syncthreads();
#pragma unroll
        for (int u = 0; u < 4; u++) {
            int f = tid + (u << 8);
            int r = f >> 3, kv = (f & 7) << 2;
            float4 a4 = *(const float4*)(A + (size_t)(m0 + r) * Dx + k0 + kv);
            *(float4*)&As[r * PDA + kv] =
                make_float4(tf32r(a4.x), tf32r(a4.y), tf32r(a4.z), tf32r(a4.w));
            int kk = f >> 5, nv = (f & 31) << 2;
            float4 w4 = *(const float4*)(W + (size_t)(k0 + kk) * Dx + n0 + nv);
            *(float4*)&Ws[kk * PDW + nv] =
                make_float4(tf32r(w4.x), tf32r(w4.y), tf32r(w4.z), tf32r(w4.w));
        }
        __syncthreads();
#pragma unroll
        for (int ks = 0; ks < 4; ks++) {
            unsigned a[2][4];
#pragma unroll
            for (int mf = 0; mf < 2; mf++) {
                int rb = (wm + (mf << 4) + g) * PDA + (ks << 3) + t;
                a[mf][0] = ASU(As[rb]);
                a[mf][1] = ASU(As[rb + 8 * PDA]);
                a[mf][2] = ASU(As[rb + 4]);
                a[mf][3] = ASU(As[rb + 8 * PDA + 4]);
            }
#pragma unroll
            for (int nt = 0; nt < 8; nt++) {
                int cb = ((ks << 3) + t) * PDW + wn + (nt << 3) + g;
                unsigned b0 = ASU(Ws[cb]);
                unsigned b1 = ASU(Ws[cb + 4 * PDW]);
                mma8(acc[0][nt], a[0][0], a[0][1], a[0][2], a[0][3], b0, b1);
                mma8(acc[1][nt], a[1][0], a[1][1], a[1][2], a[1][3], b0, b1);
            }
        }
    }
#pragma unroll
    for (int mf = 0; mf < 2; mf++)
#pragma unroll
        for (int nt = 0; nt < 8; nt++) {
            int row = m0 + wm + (mf << 4) + g;
            int col = n0 + wn + (nt << 3) + 2 * t;
            *(float2*)(C + (size_t)row * Dx + col) =
                make_float2(acc[mf][nt][0], acc[mf][nt][1]);
            *(float2*)(C + (size_t)(row + 8) * Dx + col) =
                make_float2(acc[mf][nt][2], acc[mf][nt][3]);
        }
}

__global__ __launch_bounds__(256, 2) void qkv_gemm(
    const float* __restrict__ q, const float* __restrict__ k,
    const float* __restrict__ v, const float* __restrict__ wq,
    const float* __restrict__ wk, const float* __restrict__ wv)
{
    const float *A, *W;
    float* C;
    if (blockIdx.z == 0)      { A = q; W = wq; C = g_Qp; }
    else if (blockIdx.z == 1) { A = k; W = wk; C = g_Kp; }
    else                      { A = v; W = wv; C = g_Vp; }
    gemm_body(A, W, C);
}

__global__ __launch_bounds__(256, 2) void out_gemm(
    const float* __restrict__ A, const float* __restrict__ W,
    float* __restrict__ C)
{
    gemm_body(A, W, C);
}

// ---------------------------------------------------------------------------
// 3) Flash attention, fp16 MMA (fp32 accum). CTA = (b, h, 64 q rows), 4 warps.
//    Q fragments in registers (loop-invariant). K natural [s][d] feeds B-frags
//    via ldmatrix; V natural [s][d] feeds P@V B-frags via ldmatrix.trans.
//    P stays in registers (C-frag == A-frag layout for f16 k16).
// ---------------------------------------------------------------------------
__global__ __launch_bounds__(128, 4) void attn_f16() {
    __shared__ __align__(16) unsigned short Ks[64 * KVS];
    __shared__ __align__(16) unsigned short Vs[64 * KVS];

    const int tid = threadIdx.x, warp = tid >> 5, lane = tid & 31;
    const int g = lane >> 2, t = lane & 3;
    const int q0 = blockIdx.x << 6, h = blockIdx.y, b = blockIdx.z;
    const int rw = warp << 4;
    const size_t baseQ  = ((size_t)b * Sx + q0) * Dx + (size_t)h * DKx;
    const size_t baseKV = (size_t)b * Sx * Dx + (size_t)h * DKx;

    // Q fragments, loop-invariant: 4 k-steps x 4 regs (half2)
    unsigned qa[4][4];
    {
        const float* Q0 = g_Qp + baseQ + (size_t)(rw + g) * Dx;
        const float* Q1 = Q0 + 8 * Dx;
#pragma unroll
        for (int ks = 0; ks < 4; ks++) {
            float2 x0 = *(const float2*)(Q0 + 16 * ks + 2 * t);
            float2 x1 = *(const float2*)(Q1 + 16 * ks + 2 * t);
            float2 x2 = *(const float2*)(Q0 + 16 * ks + 8 + 2 * t);
            float2 x3 = *(const float2*)(Q1 + 16 * ks + 8 + 2 * t);
            qa[ks][0] = h2u(x0.x, x0.y);
            qa[ks][1] = h2u(x1.x, x1.y);
            qa[ks][2] = h2u(x2.x, x2.y);
            qa[ks][3] = h2u(x3.x, x3.y);
        }
    }

    // ldmatrix lane-address constants
    const unsigned ksBase = (unsigned)__cvta_generic_to_shared(Ks);
    const unsigned vsBase = (unsigned)__cvta_generic_to_shared(Vs);
    const int r7 = lane & 7, mq = lane >> 3;
    // K (non-trans): matrix m: row = 8nt + ((m>>1)<<3) + r7, col = 16ks + ((m&1)<<3)
    const unsigned koff = ksBase +
        ((((mq >> 1) << 3) + r7) * KVS + ((mq & 1) << 3)) * 2u;
    // V (trans): matrix m: row = 16ks + ((m&1)<<3) + r7, col = 8nt + ((m>>1)<<3)
    const unsigned voff = vsBase +
        ((((mq & 1) << 3) + r7) * KVS + ((mq >> 1) << 3)) * 2u;

    float o[8][4] = {};
    float mr0 = -INFINITY, mr1 = -INFINITY, l0 = 0.f, l1 = 0.f;
    const size_t mb0 = ((size_t)b * Sx + q0 + rw + g) * SWx;
    const size_t mb1 = mb0 + (size_t)8 * SWx;

    for (int kt = 0; kt < Sx; kt += 64) {
        __syncthreads();  // all warps done reading previous K/V tiles
#pragma unroll
        for (int u = 0; u < 8; u++) {
            int f = tid + (u << 7);
            int r = f >> 4, dv = (f & 15) << 2;
            size_t gofs = baseKV + (size_t)(kt + r) * Dx + dv;
            float4 k4 = *(const float4*)(g_Kp + gofs);
            *(uint2*)&Ks[r * KVS + dv] =
                make_uint2(h2u(k4.x, k4.y), h2u(k4.z, k4.w));
            float4 v4 = *(const float4*)(g_Vp + gofs);
            *(uint2*)&Vs[r * KVS + dv] =
                make_uint2(h2u(v4.x, v4.y), h2u(v4.z, v4.w));
        }
        __syncthreads();

        // S = Q @ K^T
        float sa[8][4] = {};
#pragma unroll
        for (int ks = 0; ks < 4; ks++) {
#pragma unroll
            for (int nt = 0; nt < 8; nt += 2) {
                unsigned b0, b1, b2, b3;
                ldsm4(b0, b1, b2, b3,
                      koff + (unsigned)(nt * (8 * KVS) + ks * 16) * 2u);
                mma16(sa[nt],     qa[ks][0], qa[ks][1], qa[ks][2], qa[ks][3], b0, b1);
                mma16(sa[nt + 1], qa[ks][0], qa[ks][1], qa[ks][2], qa[ks][3], b2, b3);
            }
        }

        // Scale + mask (masked -> -1e9, exact reference semantics)
        const int wi = kt >> 5;
        unsigned m00 = g_mb[mb0 + wi], m01 = g_mb[mb0 + wi + 1];
        unsigned m10 = g_mb[mb1 + wi], m11 = g_mb[mb1 + wi + 1];
#pragma unroll
        for (int nt = 0; nt < 8; nt++) {
            int c0 = (nt << 3) + 2 * t;
            unsigned wr0 = (c0 < 32) ? m00 : m01;
            unsigned wr1 = (c0 < 32) ? m10 : m11;
            int bit = c0 & 31;
            sa[nt][0] = ((wr0 >> bit) & 1u)       ? sa[nt][0] * 0.125f : -1e9f;
            sa[nt][1] = ((wr0 >> (bit + 1)) & 1u) ? sa[nt][1] * 0.125f : -1e9f;
            sa[nt][2] = ((wr1 >> bit) & 1u)       ? sa[nt][2] * 0.125f : -1e9f;
            sa[nt][3] = ((wr1 >> (bit + 1)) & 1u) ? sa[nt][3] * 0.125f : -1e9f;
        }

        // Online softmax (rows rw+g and rw+g+8); overwrite sa with P
        float t0 = -INFINITY, t1 = -INFINITY;
#pragma unroll
        for (int nt = 0; nt < 8; nt++) {
            t0 = fmaxf(t0, fmaxf(sa[nt][0], sa[nt][1]));
            t1 = fmaxf(t1, fmaxf(sa[nt][2], sa[nt][3]));
        }
        t0 = fmaxf(t0, __shfl_xor_sync(0xffffffffu, t0, 1));
        t0 = fmaxf(t0, __shfl_xor_sync(0xffffffffu, t0, 2));
        t1 = fmaxf(t1, __shfl_xor_sync(0xffffffffu, t1, 1));
        t1 = fmaxf(t1, __shfl_xor_sync(0xffffffffu, t1, 2));
        float mn0 = fmaxf(mr0, t0), mn1 = fmaxf(mr1, t1);
        float corr0 = __expf(mr0 - mn0), corr1 = __expf(mr1 - mn1);
        float ps0 = 0.f, ps1 = 0.f;
#pragma unroll
        for (int nt = 0; nt < 8; nt++) {
            sa[nt][0] = __expf(sa[nt][0] - mn0);
            sa[nt][1] = __expf(sa[nt][1] - mn0);
            sa[nt][2] = __expf(sa[nt][2] - mn1);
            sa[nt][3] = __expf(sa[nt][3] - mn1);
            ps0 += sa[nt][0] + sa[nt][1];
            ps1 += sa[nt][2] + sa[nt][3];
        }
        ps0 += __shfl_xor_sync(0xffffffffu, ps0, 1);
        ps0 += __shfl_xor_sync(0xffffffffu, ps0, 2);
        ps1 += __shfl_xor_sync(0xffffffffu, ps1, 1);
        ps1 += __shfl_xor_sync(0xffffffffu, ps1, 2);
        l0 = l0 * corr0 + ps0;
        l1 = l1 * corr1 + ps1;
        mr0 = mn0; mr1 = mn1;
#pragma unroll
        for (int nt = 0; nt < 8; nt++) {
            o[nt][0] *= corr0; o[nt][1] *= corr0;
            o[nt][2] *= corr1; o[nt][3] *= corr1;
        }

        // O += P @ V : P A-frags straight from registers (C-frag == A-frag)
#pragma unroll
        for (int ks = 0; ks < 4; ks++) {
            unsigned a0 = h2u(sa[2 * ks][0],     sa[2 * ks][1]);
            unsigned a1 = h2u(sa[2 * ks][2],     sa[2 * ks][3]);
            unsigned a2 = h2u(sa[2 * ks + 1][0], sa[2 * ks + 1][1]);
            unsigned a3 = h2u(sa[2 * ks + 1][2], sa[2 * ks + 1][3]);
#pragma unroll
            for (int nt = 0; nt < 8; nt += 2) {
                unsigned b0, b1, b2, b3;
                ldsm4t(b0, b1, b2, b3,
                       voff + (unsigned)(ks * (16 * KVS) + nt * 8) * 2u);
                mma16(o[nt],     a0, a1, a2, a3, b0, b1);
                mma16(o[nt + 1], a0, a1, a2, a3, b2, b3);
            }
        }
    }

    // Normalize + store
    float i0 = 1.f / l0, i1 = 1.f / l1;
#pragma unroll
    for (int nt = 0; nt < 8; nt++) {
        int c0 = (nt << 3) + 2 * t;
        *(float2*)(g_AO + baseQ + (size_t)(rw + g)     * Dx + c0) =
            make_float2(o[nt][0] * i0, o[nt][1] * i0);
        *(float2*)(g_AO + baseQ + (size_t)(rw + g + 8) * Dx + c0) =
            make_float2(o[nt][2] * i1, o[nt][3] * i1);
    }
}

// ---------------------------------------------------------------------------
// Launch
// ---------------------------------------------------------------------------
extern "C" void kernel_launch(void* const* d_in, const int* in_sizes, int n_in,
                              void* d_out, int out_size) {
    const float* q    = (const float*)d_in[0];
    const float* k    = (const float*)d_in[1];
    const float* v    = (const float*)d_in[2];
    const int*   mask = (const int*)  d_in[3];
    const float* wq   = (const float*)d_in[4];
    const float* wk   = (const float*)d_in[5];
    const float* wv   = (const float*)d_in[6];
    const float* wo   = (const float*)d_in[7];

    float* AO;
    cudaGetSymbolAddress((void**)&AO, g_AO);

    // 1) mask compression
    mask_bits_kernel<<<(Bx * Sx * Sx) / 256, 256>>>(mask);

    // 2) fused Q/K/V projections (tf32 MMA, 128x128 tiles)
    qkv_gemm<<<dim3(Dx / 128, (Bx * Sx) / 128, 3), 256>>>(q, k, v, wq, wk, wv);

    // 3) attention (fp16 MMA flash, 64 q-rows per CTA, 4 warps)
    attn_f16<<<dim3(Sx / 64, Hx, Bx), 128>>>();

    // 4) output projection -> d_out
    out_gemm<<<dim3(Dx / 128, (Bx * Sx) / 128), 256>>>(AO, wo, (float*)d_out);
}

// round 15
// speedup vs baseline: 2.5991x; 1.0392x over previous
#include <cuda_runtime.h>
#include <cuda_fp16.h>
#include <math.h>

// Problem constants
#define Bx  2
#define Sx  4096
#define Dx  512
#define Hx  8
#define DKx 64
#define SWx 128   // Sx/32 mask words per row

// GEMM tiling (tf32 path)
#define PDA 36    // A stage row stride (36 = 4 mod 32)
#define PDW 132   // W stage row stride (132 = 4 mod 32)

// Attention smem stride in halves: 72 -> ldmatrix phases conflict-free
#define KVS 72

// Scratch (no cudaMalloc allowed). Q/K/V stored fp16 by the projections.
__device__ __half    g_Qh[Bx * Sx * Dx];
__device__ __half    g_Kh[Bx * Sx * Dx];
__device__ __half    g_Vh[Bx * Sx * Dx];
__device__ float     g_AO[Bx * Sx * Dx];
__device__ unsigned  g_mb[Bx * Sx * SWx];

// ---------------------------------------------------------------------------
// Helpers
// ---------------------------------------------------------------------------
__device__ __forceinline__ float tf32r(float x) {
    unsigned u;
    asm("cvt.rna.tf32.f32 %0, %1;" : "=r"(u) : "f"(x));
    return __uint_as_float(u);
}
__device__ __forceinline__ void mma8(float* c, unsigned a0, unsigned a1,
                                     unsigned a2, unsigned a3,
                                     unsigned b0, unsigned b1) {
    asm volatile(
        "mma.sync.aligned.m16n8k8.row.col.f32.tf32.tf32.f32 "
        "{%0,%1,%2,%3}, {%4,%5,%6,%7}, {%8,%9}, {%0,%1,%2,%3};\n"
        : "+f"(c[0]), "+f"(c[1]), "+f"(c[2]), "+f"(c[3])
        : "r"(a0), "r"(a1), "r"(a2), "r"(a3), "r"(b0), "r"(b1));
}
__device__ __forceinline__ void mma16(float* c, unsigned a0, unsigned a1,
                                      unsigned a2, unsigned a3,
                                      unsigned b0, unsigned b1) {
    asm volatile(
        "mma.sync.aligned.m16n8k16.row.col.f32.f16.f16.f32 "
        "{%0,%1,%2,%3}, {%4,%5,%6,%7}, {%8,%9}, {%0,%1,%2,%3};\n"
        : "+f"(c[0]), "+f"(c[1]), "+f"(c[2]), "+f"(c[3])
        : "r"(a0), "r"(a1), "r"(a2), "r"(a3), "r"(b0), "r"(b1));
}
__device__ __forceinline__ unsigned h2u(float a, float b) {
    __half2 h = __floats2half2_rn(a, b);
    return *reinterpret_cast<unsigned*>(&h);
}
__device__ __forceinline__ void ldsm4(unsigned& r0, unsigned& r1,
                                      unsigned& r2, unsigned& r3, unsigned addr) {
    asm volatile("ldmatrix.sync.aligned.m8n8.x4.shared.b16 {%0,%1,%2,%3}, [%4];"
                 : "=r"(r0), "=r"(r1), "=r"(r2), "=r"(r3) : "r"(addr));
}
__device__ __forceinline__ void ldsm4t(unsigned& r0, unsigned& r1,
                                       unsigned& r2, unsigned& r3, unsigned addr) {
    asm volatile("ldmatrix.sync.aligned.m8n8.x4.trans.shared.b16 {%0,%1,%2,%3}, [%4];"
                 : "=r"(r0), "=r"(r1), "=r"(r2), "=r"(r3) : "r"(addr));
}
#define ASU(x) __float_as_uint(x)

// ---------------------------------------------------------------------------
// 1) mask (int32 [B,S,S]) -> bitmask. One coalesced pass.
// ---------------------------------------------------------------------------
__global__ void mask_bits_kernel(const int* __restrict__ mask) {
    int idx = blockIdx.x * 256 + threadIdx.x;
    int m = mask[idx];
    unsigned w = __ballot_sync(0xffffffffu, m != 0);
    if ((threadIdx.x & 31) == 0) g_mb[idx >> 5] = w;
}

// ---------------------------------------------------------------------------
// 2) tf32 MMA GEMM: 128x128 CTA tile, 8 warps, K-chunk 32.
//    Templated epilogue: HALF_OUT stores __half (same rounding point the
//    attention staging used before), else fp32.
// ---------------------------------------------------------------------------
template <bool HALF_OUT>
__device__ __forceinline__ void gemm_body(const float* __restrict__ A,
                                          const float* __restrict__ W,
                                          void* __restrict__ Cv) {
    __shared__ __align__(16) float As[128 * PDA];
    __shared__ __align__(16) float Ws[32 * PDW];

    const int tid = threadIdx.x, warp = tid >> 5, lane = tid & 31;
    const int g = lane >> 2, t = lane & 3;
    const int m0 = blockIdx.y << 7, n0 = blockIdx.x << 7;
    const int wm = (warp & 3) << 5, wn = (warp >> 2) << 6;

    float acc[2][8][4] = {};

    for (int k0 = 0; k0 < Dx; k0 += 32) {
        __syncthreads();
#pragma unroll
        for (int u = 0; u < 4; u++) {
            int f = tid + (u << 8);
            int r = f >> 3, kv = (f & 7) << 2;
            float4 a4 = *(const float4*)(A + (size_t)(m0 + r) * Dx + k0 + kv);
            *(float4*)&As[r * PDA + kv] =
                make_float4(tf32r(a4.x), tf32r(a4.y), tf32r(a4.z), tf32r(a4.w));
            int kk = f >> 5, nv = (f & 31) << 2;
            float4 w4 = *(const float4*)(W + (size_t)(k0 + kk) * Dx + n0 + nv);
            *(float4*)&Ws[kk * PDW + nv] =
                make_float4(tf32r(w4.x), tf32r(w4.y), tf32r(w4.z), tf32r(w4.w));
        }
        __syncthreads();
#pragma unroll
        for (int ks = 0; ks < 4; ks++) {
            unsigned a[2][4];
#pragma unroll
            for (int mf = 0; mf < 2; mf++) {
                int rb = (wm + (mf << 4) + g) * PDA + (ks << 3) + t;
                a[mf][0] = ASU(As[rb]);
                a[mf][1] = ASU(As[rb + 8 * PDA]);
                a[mf][2] = ASU(As[rb + 4]);
                a[mf][3] = ASU(As[rb + 8 * PDA + 4]);
            }
#pragma unroll
            for (int nt = 0; nt < 8; nt++) {
                int cb = ((ks << 3) + t) * PDW + wn + (nt << 3) + g;
                unsigned b0 = ASU(Ws[cb]);
                unsigned b1 = ASU(Ws[cb + 4 * PDW]);
                mma8(acc[0][nt], a[0][0], a[0][1], a[0][2], a[0][3], b0, b1);
                mma8(acc[1][nt], a[1][0], a[1][1], a[1][2], a[1][3], b0, b1);
            }
        }
    }
#pragma unroll
    for (int mf = 0; mf < 2; mf++)
#pragma unroll
        for (int nt = 0; nt < 8; nt++) {
            int row = m0 + wm + (mf << 4) + g;
            int col = n0 + wn + (nt << 3) + 2 * t;
            if (HALF_OUT) {
                __half* C = (__half*)Cv;
                *(unsigned*)(C + (size_t)row * Dx + col) =
                    h2u(acc[mf][nt][0], acc[mf][nt][1]);
                *(unsigned*)(C + (size_t)(row + 8) * Dx + col) =
                    h2u(acc[mf][nt][2], acc[mf][nt][3]);
            } else {
                float* C = (float*)Cv;
                *(float2*)(C + (size_t)row * Dx + col) =
                    make_float2(acc[mf][nt][0], acc[mf][nt][1]);
                *(float2*)(C + (size_t)(row + 8) * Dx + col) =
                    make_float2(acc[mf][nt][2], acc[mf][nt][3]);
            }
        }
}

__global__ __launch_bounds__(256, 2) void qkv_gemm(
    const float* __restrict__ q, const float* __restrict__ k,
    const float* __restrict__ v, const float* __restrict__ wq,
    const float* __restrict__ wk, const float* __restrict__ wv)
{
    const float *A, *W;
    __half* C;
    if (blockIdx.z == 0)      { A = q; W = wq; C = g_Qh; }
    else if (blockIdx.z == 1) { A = k; W = wk; C = g_Kh; }
    else                      { A = v; W = wv; C = g_Vh; }
    gemm_body<true>(A, W, C);
}

__global__ __launch_bounds__(256, 2) void out_gemm(
    const float* __restrict__ A, const float* __restrict__ W,
    float* __restrict__ C)
{
    gemm_body<false>(A, W, C);
}

// ---------------------------------------------------------------------------
// 3) Flash attention, fp16 MMA. CTA = (b, h, 128 q rows), 8 warps (16 rows
//    each — identical per-warp code to the proven R8 kernel). K/V arrive as
//    fp16: staging is pure uint4 copies, no conversion.
// ---------------------------------------------------------------------------
__global__ __launch_bounds__(256) void attn_f16() {
    __shared__ __align__(16) unsigned short Ks[64 * KVS];
    __shared__ __align__(16) unsigned short Vs[64 * KVS];

    const int tid = threadIdx.x, warp = tid >> 5, lane = tid & 31;
    const int g = lane >> 2, t = lane & 3;
    const int q0 = blockIdx.x << 7, h = blockIdx.y, b = blockIdx.z;
    const int rw = warp << 4;
    const size_t baseQ  = ((size_t)b * Sx + q0) * Dx + (size_t)h * DKx;
    const size_t baseKV = (size_t)b * Sx * Dx + (size_t)h * DKx;

    // Q fragments, loop-invariant: 4 k-steps x 4 regs (half2), direct fp16 loads
    unsigned qa[4][4];
    {
        const __half* Q0 = g_Qh + baseQ + (size_t)(rw + g) * Dx;
        const __half* Q1 = Q0 + 8 * Dx;
#pragma unroll
        for (int ks = 0; ks < 4; ks++) {
            qa[ks][0] = *(const unsigned*)(Q0 + 16 * ks + 2 * t);
            qa[ks][1] = *(const unsigned*)(Q1 + 16 * ks + 2 * t);
            qa[ks][2] = *(const unsigned*)(Q0 + 16 * ks + 8 + 2 * t);
            qa[ks][3] = *(const unsigned*)(Q1 + 16 * ks + 8 + 2 * t);
        }
    }

    // ldmatrix lane-address constants (same proven mapping as R8)
    const unsigned ksBase = (unsigned)__cvta_generic_to_shared(Ks);
    const unsigned vsBase = (unsigned)__cvta_generic_to_shared(Vs);
    const int r7 = lane & 7, mq = lane >> 3;
    const unsigned koff = ksBase +
        ((((mq >> 1) << 3) + r7) * KVS + ((mq & 1) << 3)) * 2u;
    const unsigned voff = vsBase +
        ((((mq & 1) << 3) + r7) * KVS + ((mq >> 1) << 3)) * 2u;

    float o[8][4] = {};
    float mr0 = -INFINITY, mr1 = -INFINITY, l0 = 0.f, l1 = 0.f;
    const size_t mb0 = ((size_t)b * Sx + q0 + rw + g) * SWx;
    const size_t mb1 = mb0 + (size_t)8 * SWx;

    for (int kt = 0; kt < Sx; kt += 64) {
        __syncthreads();  // all warps done reading previous K/V tiles
        // Stage K/V: 64 rows x 64 halves each = 512 uint4 per tile, 256 threads
#pragma unroll
        for (int u = 0; u < 2; u++) {
            int f = tid + (u << 8);
            int r = f >> 3, dv = (f & 7) << 3;
            size_t gofs = baseKV + (size_t)(kt + r) * Dx + dv;
            *(uint4*)&Ks[r * KVS + dv] = *(const uint4*)(g_Kh + gofs);
            *(uint4*)&Vs[r * KVS + dv] = *(const uint4*)(g_Vh + gofs);
        }
        __syncthreads();

        // S = Q @ K^T
        float sa[8][4] = {};
#pragma unroll
        for (int ks = 0; ks < 4; ks++) {
#pragma unroll
            for (int nt = 0; nt < 8; nt += 2) {
                unsigned b0, b1, b2, b3;
                ldsm4(b0, b1, b2, b3,
                      koff + (unsigned)(nt * (8 * KVS) + ks * 16) * 2u);
                mma16(sa[nt],     qa[ks][0], qa[ks][1], qa[ks][2], qa[ks][3], b0, b1);
                mma16(sa[nt + 1], qa[ks][0], qa[ks][1], qa[ks][2], qa[ks][3], b2, b3);
            }
        }

        // Scale + mask (masked -> -1e9, exact reference semantics)
        const int wi = kt >> 5;
        unsigned m00 = g_mb[mb0 + wi], m01 = g_mb[mb0 + wi + 1];
        unsigned m10 = g_mb[mb1 + wi], m11 = g_mb[mb1 + wi + 1];
#pragma unroll
        for (int nt = 0; nt < 8; nt++) {
            int c0 = (nt << 3) + 2 * t;
            unsigned wr0 = (c0 < 32) ? m00 : m01;
            unsigned wr1 = (c0 < 32) ? m10 : m11;
            int bit = c0 & 31;
            sa[nt][0] = ((wr0 >> bit) & 1u)       ? sa[nt][0] * 0.125f : -1e9f;
            sa[nt][1] = ((wr0 >> (bit + 1)) & 1u) ? sa[nt][1] * 0.125f : -1e9f;
            sa[nt][2] = ((wr1 >> bit) & 1u)       ? sa[nt][2] * 0.125f : -1e9f;
            sa[nt][3] = ((wr1 >> (bit + 1)) & 1u) ? sa[nt][3] * 0.125f : -1e9f;
        }

        // Online softmax (rows rw+g and rw+g+8); overwrite sa with P
        float t0 = -INFINITY, t1 = -INFINITY;
#pragma unroll
        for (int nt = 0; nt < 8; nt++) {
            t0 = fmaxf(t0, fmaxf(sa[nt][0], sa[nt][1]));
            t1 = fmaxf(t1, fmaxf(sa[nt][2], sa[nt][3]));
        }
        t0 = fmaxf(t0, __shfl_xor_sync(0xffffffffu, t0, 1));
        t0 = fmaxf(t0, __shfl_xor_sync(0xffffffffu, t0, 2));
        t1 = fmaxf(t1, __shfl_xor_sync(0xffffffffu, t1, 1));
        t1 = fmaxf(t1, __shfl_xor_sync(0xffffffffu, t1, 2));
        float mn0 = fmaxf(mr0, t0), mn1 = fmaxf(mr1, t1);
        float corr0 = __expf(mr0 - mn0), corr1 = __expf(mr1 - mn1);
        float ps0 = 0.f, ps1 = 0.f;
#pragma unroll
        for (int nt = 0; nt < 8; nt++) {
            sa[nt][0] = __expf(sa[nt][0] - mn0);
            sa[nt][1] = __expf(sa[nt][1] - mn0);
            sa[nt][2] = __expf(sa[nt][2] - mn1);
            sa[nt][3] = __expf(sa[nt][3] - mn1);
            ps0 += sa[nt][0] + sa[nt][1];
            ps1 += sa[nt][2] + sa[nt][3];
        }
        ps0 += __shfl_xor_sync(0xffffffffu, ps0, 1);
        ps0 += __shfl_xor_sync(0xffffffffu, ps0, 2);
        ps1 += __shfl_xor_sync(0xffffffffu, ps1, 1);
        ps1 += __shfl_xor_sync(0xffffffffu, ps1, 2);
        l0 = l0 * corr0 + ps0;
        l1 = l1 * corr1 + ps1;
        mr0 = mn0; mr1 = mn1;
#pragma unroll
        for (int nt = 0; nt < 8; nt++) {
            o[nt][0] *= corr0; o[nt][1] *= corr0;
            o[nt][2] *= corr1; o[nt][3] *= corr1;
        }

        // O += P @ V : P A-frags straight from registers (C-frag == A-frag)
#pragma unroll
        for (int ks = 0; ks < 4; ks++) {
            unsigned a0 = h2u(sa[2 * ks][0],     sa[2 * ks][1]);
            unsigned a1 = h2u(sa[2 * ks][2],     sa[2 * ks][3]);
            unsigned a2 = h2u(sa[2 * ks + 1][0], sa[2 * ks + 1][1]);
            unsigned a3 = h2u(sa[2 * ks + 1][2], sa[2 * ks + 1][3]);
#pragma unroll
            for (int nt = 0; nt < 8; nt += 2) {
                unsigned b0, b1, b2, b3;
                ldsm4t(b0, b1, b2, b3,
                       voff + (unsigned)(ks * (16 * KVS) + nt * 8) * 2u);
                mma16(o[nt],     a0, a1, a2, a3, b0, b1);
                mma16(o[nt + 1], a0, a1, a2, a3, b2, b3);
            }
        }
    }

    // Normalize + store (fp32 for the output projection)
    float i0 = 1.f / l0, i1 = 1.f / l1;
#pragma unroll
    for (int nt = 0; nt < 8; nt++) {
        int c0 = (nt << 3) + 2 * t;
        *(float2*)(g_AO + baseQ + (size_t)(rw + g)     * Dx + c0) =
            make_float2(o[nt][0] * i0, o[nt][1] * i0);
        *(float2*)(g_AO + baseQ + (size_t)(rw + g + 8) * Dx + c0) =
            make_float2(o[nt][2] * i1, o[nt][3] * i1);
    }
}

// ---------------------------------------------------------------------------
// Launch
// ---------------------------------------------------------------------------
extern "C" void kernel_launch(void* const* d_in, const int* in_sizes, int n_in,
                              void* d_out, int out_size) {
    const float* q    = (const float*)d_in[0];
    const float* k    = (const float*)d_in[1];
    const float* v    = (const float*)d_in[2];
    const int*   mask = (const int*)  d_in[3];
    const float* wq   = (const float*)d_in[4];
    const float* wk   = (const float*)d_in[5];
    const float* wv   = (const float*)d_in[6];
    const float* wo   = (const float*)d_in[7];

    float* AO;
    cudaGetSymbolAddress((void**)&AO, g_AO);

    // 1) mask compression
    mask_bits_kernel<<<(Bx * Sx * Sx) / 256, 256>>>(mask);

    // 2) fused Q/K/V projections (tf32 MMA, fp16 outputs)
    qkv_gemm<<<dim3(Dx / 128, (Bx * Sx) / 128, 3), 256>>>(q, k, v, wq, wk, wv);

    // 3) attention (fp16 MMA flash, 128 q-rows per CTA, 8 warps)
    attn_f16<<<dim3(Sx / 128, Hx, Bx), 256>>>();

    // 4) output projection -> d_out (fp32)
    out_gemm<<<dim3(Dx / 128, (Bx * Sx) / 128), 256>>>(AO, wo, (float*)d_out);
}

// round 17
// speedup vs baseline: 2.7669x; 1.0646x over previous
#include <cuda_runtime.h>
#include <cuda_fp16.h>
#include <math.h>

// Problem constants
#define Bx  2
#define Sx  4096
#define Dx  512
#define Hx  8
#define DKx 64
#define SWx 128   // Sx/32 mask words per row

// GEMM tiling (tf32 path)
#define PDA 36    // A stage row stride (36 = 4 mod 32)
#define PDW 132   // W stage row stride (132 = 4 mod 32)

// Attention smem stride in halves: 72 -> ldmatrix phases conflict-free
#define KVS 72
#define TILE_HALVES (64 * KVS)          // halves per K or V tile
#define TILE_BYTES  (TILE_HALVES * 2)   // 9216 bytes

// Scratch (no cudaMalloc allowed). Q/K/V stored fp16 by the projections.
__device__ __half    g_Qh[Bx * Sx * Dx];
__device__ __half    g_Kh[Bx * Sx * Dx];
__device__ __half    g_Vh[Bx * Sx * Dx];
__device__ float     g_AO[Bx * Sx * Dx];
__device__ unsigned  g_mb[Bx * Sx * SWx];

// ---------------------------------------------------------------------------
// Helpers
// ---------------------------------------------------------------------------
__device__ __forceinline__ float tf32r(float x) {
    unsigned u;
    asm("cvt.rna.tf32.f32 %0, %1;" : "=r"(u) : "f"(x));
    return __uint_as_float(u);
}
__device__ __forceinline__ void mma8(float* c, unsigned a0, unsigned a1,
                                     unsigned a2, unsigned a3,
                                     unsigned b0, unsigned b1) {
    asm volatile(
        "mma.sync.aligned.m16n8k8.row.col.f32.tf32.tf32.f32 "
        "{%0,%1,%2,%3}, {%4,%5,%6,%7}, {%8,%9}, {%0,%1,%2,%3};\n"
        : "+f"(c[0]), "+f"(c[1]), "+f"(c[2]), "+f"(c[3])
        : "r"(a0), "r"(a1), "r"(a2), "r"(a3), "r"(b0), "r"(b1));
}
__device__ __forceinline__ void mma16(float* c, unsigned a0, unsigned a1,
                                      unsigned a2, unsigned a3,
                                      unsigned b0, unsigned b1) {
    asm volatile(
        "mma.sync.aligned.m16n8k16.row.col.f32.f16.f16.f32 "
        "{%0,%1,%2,%3}, {%4,%5,%6,%7}, {%8,%9}, {%0,%1,%2,%3};\n"
        : "+f"(c[0]), "+f"(c[1]), "+f"(c[2]), "+f"(c[3])
        : "r"(a0), "r"(a1), "r"(a2), "r"(a3), "r"(b0), "r"(b1));
}
__device__ __forceinline__ unsigned h2u(float a, float b) {
    __half2 h = __floats2half2_rn(a, b);
    return *reinterpret_cast<unsigned*>(&h);
}
__device__ __forceinline__ void ldsm4(unsigned& r0, unsigned& r1,
                                      unsigned& r2, unsigned& r3, unsigned addr) {
    asm volatile("ldmatrix.sync.aligned.m8n8.x4.shared.b16 {%0,%1,%2,%3}, [%4];"
                 : "=r"(r0), "=r"(r1), "=r"(r2), "=r"(r3) : "r"(addr));
}
__device__ __forceinline__ void ldsm4t(unsigned& r0, unsigned& r1,
                                       unsigned& r2, unsigned& r3, unsigned addr) {
    asm volatile("ldmatrix.sync.aligned.m8n8.x4.trans.shared.b16 {%0,%1,%2,%3}, [%4];"
                 : "=r"(r0), "=r"(r1), "=r"(r2), "=r"(r3) : "r"(addr));
}
__device__ __forceinline__ void cpasync16(unsigned saddr, const void* gptr) {
    asm volatile("cp.async.cg.shared.global [%0], [%1], 16;"
                 :: "r"(saddr), "l"(gptr));
}
#define CP_COMMIT() asm volatile("cp.async.commit_group;" ::: "memory")
#define CP_WAIT0()  asm volatile("cp.async.wait_group 0;" ::: "memory")
#define ASU(x) __float_as_uint(x)

// ---------------------------------------------------------------------------
// 1) mask (int32 [B,S,S]) -> bitmask. One coalesced pass.
// ---------------------------------------------------------------------------
__global__ void mask_bits_kernel(const int* __restrict__ mask) {
    int idx = blockIdx.x * 256 + threadIdx.x;
    int m = mask[idx];
    unsigned w = __ballot_sync(0xffffffffu, m != 0);
    if ((threadIdx.x & 31) == 0) g_mb[idx >> 5] = w;
}

// ---------------------------------------------------------------------------
// 2) tf32 MMA GEMM: 128x128 CTA tile, 8 warps, K-chunk 32.
//    Templated epilogue: HALF_OUT stores __half, else fp32.
// ---------------------------------------------------------------------------
template <bool HALF_OUT>
__device__ __forceinline__ void gemm_body(const float* __restrict__ A,
                                          const float* __restrict__ W,
                                          void* __restrict__ Cv) {
    __shared__ __align__(16) float As[128 * PDA];
    __shared__ __align__(16) float Ws[32 * PDW];

    const int tid = threadIdx.x, warp = tid >> 5, lane = tid & 31;
    const int g = lane >> 2, t = lane & 3;
    const int m0 = blockIdx.y << 7, n0 = blockIdx.x << 7;
    const int wm = (warp & 3) << 5, wn = (warp >> 2) << 6;

    float acc[2][8][4] = {};

    for (int k0 = 0; k0 < Dx; k0 += 32) {
        __syncthreads();
#pragma unroll
        for (int u = 0; u < 4; u++) {
            int f = tid + (u << 8);
            int r = f >> 3, kv = (f & 7) << 2;
            float4 a4 = *(const float4*)(A + (size_t)(m0 + r) * Dx + k0 + kv);
            *(float4*)&As[r * PDA + kv] =
                make_float4(tf32r(a4.x), tf32r(a4.y), tf32r(a4.z), tf32r(a4.w));
            int kk = f >> 5, nv = (f & 31) << 2;
            float4 w4 = *(const float4*)(W + (size_t)(k0 + kk) * Dx + n0 + nv);
            *(float4*)&Ws[kk * PDW + nv] =
                make_float4(tf32r(w4.x), tf32r(w4.y), tf32r(w4.z), tf32r(w4.w));
        }
        __syncthreads();
#pragma unroll
        for (int ks = 0; ks < 4; ks++) {
            unsigned a[2][4];
#pragma unroll
            for (int mf = 0; mf < 2; mf++) {
                int rb = (wm + (mf << 4) + g) * PDA + (ks << 3) + t;
                a[mf][0] = ASU(As[rb]);
                a[mf][1] = ASU(As[rb + 8 * PDA]);
                a[mf][2] = ASU(As[rb + 4]);
                a[mf][3] = ASU(As[rb + 8 * PDA + 4]);
            }
#pragma unroll
            for (int nt = 0; nt < 8; nt++) {
                int cb = ((ks << 3) + t) * PDW + wn + (nt << 3) + g;
                unsigned b0 = ASU(Ws[cb]);
                unsigned b1 = ASU(Ws[cb + 4 * PDW]);
                mma8(acc[0][nt], a[0][0], a[0][1], a[0][2], a[0][3], b0, b1);
                mma8(acc[1][nt], a[1][0], a[1][1], a[1][2], a[1][3], b0, b1);
            }
        }
    }
#pragma unroll
    for (int mf = 0; mf < 2; mf++)
#pragma unroll
        for (int nt = 0; nt < 8; nt++) {
            int row = m0 + wm + (mf << 4) + g;
            int col = n0 + wn + (nt << 3) + 2 * t;
            if (HALF_OUT) {
                __half* C = (__half*)Cv;
                *(unsigned*)(C + (size_t)row * Dx + col) =
                    h2u(acc[mf][nt][0], acc[mf][nt][1]);
                *(unsigned*)(C + (size_t)(row + 8) * Dx + col) =
                    h2u(acc[mf][nt][2], acc[mf][nt][3]);
            } else {
                float* C = (float*)Cv;
                *(float2*)(C + (size_t)row * Dx + col) =
                    make_float2(acc[mf][nt][0], acc[mf][nt][1]);
                *(float2*)(C + (size_t)(row + 8) * Dx + col) =
                    make_float2(acc[mf][nt][2], acc[mf][nt][3]);
            }
        }
}

__global__ __launch_bounds__(256, 2) void qkv_gemm(
    const float* __restrict__ q, const float* __restrict__ k,
    const float* __restrict__ v, const float* __restrict__ wq,
    const float* __restrict__ wk, const float* __restrict__ wv)
{
    const float *A, *W;
    __half* C;
    if (blockIdx.z == 0)      { A = q; W = wq; C = g_Qh; }
    else if (blockIdx.z == 1) { A = k; W = wk; C = g_Kh; }
    else                      { A = v; W = wv; C = g_Vh; }
    gemm_body<true>(A, W, C);
}

__global__ __launch_bounds__(256, 2) void out_gemm(
    const float* __restrict__ A, const float* __restrict__ W,
    float* __restrict__ C)
{
    gemm_body<false>(A, W, C);
}

// ---------------------------------------------------------------------------
// 3) Flash attention, fp16 MMA, cp.async DOUBLE-BUFFERED K/V staging.
//    CTA = (b, h, 128 q rows), 8 warps. Loop: wait tile i -> one barrier ->
//    issue tile i+1 into other buffer -> compute tile i. Global-load latency
//    is hidden behind the whole compute of the previous tile.
// ---------------------------------------------------------------------------
__global__ __launch_bounds__(256) void attn_f16() {
    __shared__ __align__(16) unsigned short Ks[2 * TILE_HALVES];
    __shared__ __align__(16) unsigned short Vs[2 * TILE_HALVES];

    const int tid = threadIdx.x, warp = tid >> 5, lane = tid & 31;
    const int g = lane >> 2, t = lane & 3;
    const int q0 = blockIdx.x << 7, h = blockIdx.y, b = blockIdx.z;
    const int rw = warp << 4;
    const size_t baseQ  = ((size_t)b * Sx + q0) * Dx + (size_t)h * DKx;
    const size_t baseKV = (size_t)b * Sx * Dx + (size_t)h * DKx;

    // Per-thread staging coords (4x16B per tile: rows tid>>3 and (tid>>3)+32)
    const int sr = tid >> 3, sdv = (tid & 7) << 3;
    const unsigned ksBase = (unsigned)__cvta_generic_to_shared(Ks);
    const unsigned vsBase = (unsigned)__cvta_generic_to_shared(Vs);
    const unsigned sOfs0 = (unsigned)((sr * KVS + sdv) * 2);
    const unsigned sOfs1 = (unsigned)(((sr + 32) * KVS + sdv) * 2);

    // Prologue: issue tile 0 into buffer 0
    {
        const __half* kp = g_Kh + baseKV + (size_t)sr * Dx + sdv;
        const __half* vp = g_Vh + baseKV + (size_t)sr * Dx + sdv;
        cpasync16(ksBase + sOfs0, kp);
        cpasync16(ksBase + sOfs1, kp + 32 * Dx);
        cpasync16(vsBase + sOfs0, vp);
        cpasync16(vsBase + sOfs1, vp + 32 * Dx);
        CP_COMMIT();
    }

    // Q fragments, loop-invariant: 4 k-steps x 4 regs (half2)
    unsigned qa[4][4];
    {
        const __half* Q0 = g_Qh + baseQ + (size_t)(rw + g) * Dx;
        const __half* Q1 = Q0 + 8 * Dx;
#pragma unroll
        for (int ks = 0; ks < 4; ks++) {
            qa[ks][0] = *(const unsigned*)(Q0 + 16 * ks + 2 * t);
            qa[ks][1] = *(const unsigned*)(Q1 + 16 * ks + 2 * t);
            qa[ks][2] = *(const unsigned*)(Q0 + 16 * ks + 8 + 2 * t);
            qa[ks][3] = *(const unsigned*)(Q1 + 16 * ks + 8 + 2 * t);
        }
    }

    // ldmatrix lane-address constants (same proven mapping as R8/R15)
    const int r7 = lane & 7, mq = lane >> 3;
    const unsigned koff = ksBase +
        ((((mq >> 1) << 3) + r7) * KVS + ((mq & 1) << 3)) * 2u;
    const unsigned voff = vsBase +
        ((((mq & 1) << 3) + r7) * KVS + ((mq >> 1) << 3)) * 2u;

    float o[8][4] = {};
    float mr0 = -INFINITY, mr1 = -INFINITY, l0 = 0.f, l1 = 0.f;
    const size_t mb0 = ((size_t)b * Sx + q0 + rw + g) * SWx;
    const size_t mb1 = mb0 + (size_t)8 * SWx;

    for (int it = 0; it < Sx / 64; it++) {
        const int kt = it << 6;
        CP_WAIT0();       // tile it landed (only group outstanding at this point)
        __syncthreads();  // visible to all warps; all warps done with tile it-1

        // Issue tile it+1 into the other buffer (overlaps with compute below)
        if (it + 1 < Sx / 64) {
            const unsigned bo = (unsigned)(((it + 1) & 1) * TILE_BYTES);
            const __half* kp = g_Kh + baseKV + (size_t)(kt + 64 + sr) * Dx + sdv;
            const __half* vp = g_Vh + baseKV + (size_t)(kt + 64 + sr) * Dx + sdv;
            cpasync16(ksBase + bo + sOfs0, kp);
            cpasync16(ksBase + bo + sOfs1, kp + 32 * Dx);
            cpasync16(vsBase + bo + sOfs0, vp);
            cpasync16(vsBase + bo + sOfs1, vp + 32 * Dx);
            CP_COMMIT();
        }
        const unsigned bufo = (unsigned)((it & 1) * TILE_BYTES);

        // S = Q @ K^T
        float sa[8][4] = {};
#pragma unroll
        for (int ks = 0; ks < 4; ks++) {
#pragma unroll
            for (int nt = 0; nt < 8; nt += 2) {
                unsigned b0, b1, b2, b3;
                ldsm4(b0, b1, b2, b3,
                      koff + bufo + (unsigned)(nt * (8 * KVS) + ks * 16) * 2u);
                mma16(sa[nt],     qa[ks][0], qa[ks][1], qa[ks][2], qa[ks][3], b0, b1);
                mma16(sa[nt + 1], qa[ks][0], qa[ks][1], qa[ks][2], qa[ks][3], b2, b3);
            }
        }

        // Scale + mask (masked -> -1e9, exact reference semantics)
        const int wi = kt >> 5;
        unsigned m00 = g_mb[mb0 + wi], m01 = g_mb[mb0 + wi + 1];
        unsigned m10 = g_mb[mb1 + wi], m11 = g_mb[mb1 + wi + 1];
#pragma unroll
        for (int nt = 0; nt < 8; nt++) {
            int c0 = (nt << 3) + 2 * t;
            unsigned wr0 = (c0 < 32) ? m00 : m01;
            unsigned wr1 = (c0 < 32) ? m10 : m11;
            int bit = c0 & 31;
            sa[nt][0] = ((wr0 >> bit) & 1u)       ? sa[nt][0] * 0.125f : -1e9f;
            sa[nt][1] = ((wr0 >> (bit + 1)) & 1u) ? sa[nt][1] * 0.125f : -1e9f;
            sa[nt][2] = ((wr1 >> bit) & 1u)       ? sa[nt][2] * 0.125f : -1e9f;
            sa[nt][3] = ((wr1 >> (bit + 1)) & 1u) ? sa[nt][3] * 0.125f : -1e9f;
        }

        // Online softmax (rows rw+g and rw+g+8); overwrite sa with P
        float t0 = -INFINITY, t1 = -INFINITY;
#pragma unroll
        for (int nt = 0; nt < 8; nt++) {
            t0 = fmaxf(t0, fmaxf(sa[nt][0], sa[nt][1]));
            t1 = fmaxf(t1, fmaxf(sa[nt][2], sa[nt][3]));
        }
        t0 = fmaxf(t0, __shfl_xor_sync(0xffffffffu, t0, 1));
        t0 = fmaxf(t0, __shfl_xor_sync(0xffffffffu, t0, 2));
        t1 = fmaxf(t1, __shfl_xor_sync(0xffffffffu, t1, 1));
        t1 = fmaxf(t1, __shfl_xor_sync(0xffffffffu, t1, 2));
        float mn0 = fmaxf(mr0, t0), mn1 = fmaxf(mr1, t1);
        float corr0 = __expf(mr0 - mn0), corr1 = __expf(mr1 - mn1);
        float ps0 = 0.f, ps1 = 0.f;
#pragma unroll
        for (int nt = 0; nt < 8; nt++) {
            sa[nt][0] = __expf(sa[nt][0] - mn0);
            sa[nt][1] = __expf(sa[nt][1] - mn0);
            sa[nt][2] = __expf(sa[nt][2] - mn1);
            sa[nt][3] = __expf(sa[nt][3] - mn1);
            ps0 += sa[nt][0] + sa[nt][1];
            ps1 += sa[nt][2] + sa[nt][3];
        }
        ps0 += __shfl_xor_sync(0xffffffffu, ps0, 1);
        ps0 += __shfl_xor_sync(0xffffffffu, ps0, 2);
        ps1 += __shfl_xor_sync(0xffffffffu, ps1, 1);
        ps1 += __shfl_xor_sync(0xffffffffu, ps1, 2);
        l0 = l0 * corr0 + ps0;
        l1 = l1 * corr1 + ps1;
        mr0 = mn0; mr1 = mn1;
#pragma unroll
        for (int nt = 0; nt < 8; nt++) {
            o[nt][0] *= corr0; o[nt][1] *= corr0;
            o[nt][2] *= corr1; o[nt][3] *= corr1;
        }

        // O += P @ V : P A-frags straight from registers (C-frag == A-frag)
#pragma unroll
        for (int ks = 0; ks < 4; ks++) {
            unsigned a0 = h2u(sa[2 * ks][0],     sa[2 * ks][1]);
            unsigned a1 = h2u(sa[2 * ks][2],     sa[2 * ks][3]);
            unsigned a2 = h2u(sa[2 * ks + 1][0], sa[2 * ks + 1][1]);
            unsigned a3 = h2u(sa[2 * ks + 1][2], sa[2 * ks + 1][3]);
#pragma unroll
            for (int nt = 0; nt < 8; nt += 2) {
                unsigned b0, b1, b2, b3;
                ldsm4t(b0, b1, b2, b3,
                       voff + bufo + (unsigned)(ks * (16 * KVS) + nt * 8) * 2u);
                mma16(o[nt],     a0, a1, a2, a3, b0, b1);
                mma16(o[nt + 1], a0, a1, a2, a3, b2, b3);
            }
        }
    }

    // Normalize + store (fp32 for the output projection)
    float i0 = 1.f / l0, i1 = 1.f / l1;
#pragma unroll
    for (int nt = 0; nt < 8; nt++) {
        int c0 = (nt << 3) + 2 * t;
        *(float2*)(g_AO + baseQ + (size_t)(rw + g)     * Dx + c0) =
            make_float2(o[nt][0] * i0, o[nt][1] * i0);
        *(float2*)(g_AO + baseQ + (size_t)(rw + g + 8) * Dx + c0) =
            make_float2(o[nt][2] * i1, o[nt][3] * i1);
    }
}

// ---------------------------------------------------------------------------
// Launch
// ---------------------------------------------------------------------------
extern "C" void kernel_launch(void* const* d_in, const int* in_sizes, int n_in,
                              void* d_out, int out_size) {
    const float* q    = (const float*)d_in[0];
    const float* k    = (const float*)d_in[1];
    const float* v    = (const float*)d_in[2];
    const int*   mask = (const int*)  d_in[3];
    const float* wq   = (const float*)d_in[4];
    const float* wk   = (const float*)d_in[5];
    const float* wv   = (const float*)d_in[6];
    const float* wo   = (const float*)d_in[7];

    float* AO;
    cudaGetSymbolAddress((void**)&AO, g_AO);

    // 1) mask compression
    mask_bits_kernel<<<(Bx * Sx * Sx) / 256, 256>>>(mask);

    // 2) fused Q/K/V projections (tf32 MMA, fp16 outputs)
    qkv_gemm<<<dim3(Dx / 128, (Bx * Sx) / 128, 3), 256>>>(q, k, v, wq, wk, wv);

    // 3) attention (fp16 MMA flash, cp.async double-buffered)
    attn_f16<<<dim3(Sx / 128, Hx, Bx), 256>>>();

    // 4) output projection -> d_out (fp32)
    out_gemm<<<dim3(Dx / 128, (Bx * Sx) / 128), 256>>>(AO, wo, (float*)d_out);
}